// round 8
// baseline (speedup 1.0000x reference)
#include <cuda_runtime.h>
#include <math.h>

#define FULLMASK 0xffffffffu

// Composed register-bit CNOT relabel (wires 5..9 = reg bits 0..4), per layer:
#define RSRC(r) ( ((r)&1) \
    | (((((r)>>1)^(r))&1)<<1) \
    | (((((r)>>2)^((r)>>1)^(r))&1)<<2) \
    | (((((r)>>3)^((r)>>2))&1)<<3) \
    | (((((r)>>4)^((r)>>3)^((r)>>2))&1)<<4) )

// Frame-tracked lane-wire constants (A_k = (Mrev^-1)^k, verified round 4):
__device__ __constant__ const int MK[6][5] = {
    { 3,14,12,24,16},
    {13,26,20, 8,16},
    {23, 6,28,24,16},
    {17, 2, 4, 8,16},
    {19,14,12,24,16},
    {29,26,20, 8,16}
};
__device__ __constant__ const int SK[6][5] = {
    {1,3,7,12,28},
    {1,2,5,11,23},
    {1,3,6,14,25},
    {1,2,4,8,17},
    {1,3,7,12,29},
    {1,2,5,11,22}
};
__device__ __constant__ const int CK[6] = {16,28,23,25,17,29};
__device__ __constant__ const int MROW[5] = {1,2,5,11,22};

__device__ __forceinline__ float fast_tanh(float x) {
    float e;
    asm("ex2.approx.f32 %0, %1;" : "=f"(e) : "f"(x * 2.88539008177792681f));
    return (e - 1.0f) * __frcp_rn(e + 1.0f);
}

__device__ __forceinline__ unsigned pack_h2(float lo, float hi) {
    unsigned r;
    asm("cvt.rn.f16x2.f32 %0, %1, %2;" : "=r"(r) : "f"(hi), "f"(lo));
    return r;
}
__device__ __forceinline__ unsigned hmul2_u(unsigned a, unsigned b) {
    unsigned r;
    asm("mul.rn.f16x2 %0, %1, %2;" : "=r"(r) : "r"(a), "r"(b));
    return r;
}
__device__ __forceinline__ float2 unpack_h2(unsigned u) {
    float2 r;
    asm("{\n\t.reg .b16 h0,h1;\n\t"
        "mov.b32 {h0,h1}, %2;\n\t"
        "cvt.f32.f16 %0, h0;\n\t"
        "cvt.f32.f16 %1, h1;\n\t}"
        : "=f"(r.x), "=f"(r.y) : "r"(u));
    return r;
}

__global__ __launch_bounds__(256, 5)
void dq_kernel(const float* __restrict__ x,
               const float* __restrict__ W1,
               const float* __restrict__ b1,
               const float* __restrict__ qw,
               const float* __restrict__ W2,
               const float* __restrict__ b2,
               float* __restrict__ out)
{
    __shared__ alignas(16) float sW1[10][512];
    __shared__ float sW2[640];
    __shared__ float sb2[64];
    __shared__ float sb1[10];
    __shared__ float sqt[6][10];
    __shared__ float sCt;
    __shared__ float scc[64];

    const int tid = threadIdx.x;

#pragma unroll 4
    for (int i = tid; i < 5120; i += 256) {
        int d = i / 10, q = i - d * 10;
        sW1[q][d] = W1[i];
    }
    for (int i = tid; i < 640; i += 256) sW2[i] = W2[i];
    if (tid < 64) sb2[tid] = b2[tid];
    if (tid < 10) sb1[tid] = b1[tid];
    if (tid < 60) {
        float th = 0.5f * qw[tid];
        float s = __sinf(th), c = __cosf(th);
        sqt[tid / 10][tid % 10] = s * __frcp_rn(c);
        scc[tid] = c;
    }
    __syncthreads();
    if (tid == 0) {
        float p = 1.f;
#pragma unroll
        for (int i = 0; i < 60; i++) p *= scc[i];
        sCt = p;
    }
    __syncthreads();

    const int warp = tid >> 5;
    const int lane = tid & 31;
    const int sample = blockIdx.x * 8 + warp;
    const float* xr = x + (size_t)sample * 512;

    // ---- angles = tanh(x@W1 + b1) * pi/2; per-wire u/v ----
    const float4* x4 = (const float4*)xr;
    float4 xv[4];
#pragma unroll
    for (int t = 0; t < 4; t++) xv[t] = x4[lane + 32 * t];

    float u[10], v[10];
#pragma unroll
    for (int q = 0; q < 10; q++) {
        const float4* w4 = (const float4*)(&sW1[q][0]);
        float p = 0.f;
#pragma unroll
        for (int t = 0; t < 4; t++) {
            float4 wv = w4[lane + 32 * t];
            p = fmaf(xv[t].x, wv.x, p);
            p = fmaf(xv[t].y, wv.y, p);
            p = fmaf(xv[t].z, wv.z, p);
            p = fmaf(xv[t].w, wv.w, p);
        }
#pragma unroll
        for (int off = 16; off; off >>= 1) p += __shfl_xor_sync(FULLMASK, p, off);
        float ang = fast_tanh(p + sb1[q]) * 1.57079632679489662f;
        float hh = 0.5f * ang;
        float sn = __sinf(hh), cs = __cosf(hh);
        u[q] = (cs - sn) * 0.70710678118654752f;
        v[q] = (cs + sn) * 0.70710678118654752f;
    }

    // ---- build product state, prescaled by the total deferred cosine ----
    float st[32];
    float L = sCt;
#pragma unroll
    for (int w = 0; w < 5; w++) L *= ((lane >> w) & 1) ? v[w] : u[w];
    st[0] = L;
#pragma unroll
    for (int b = 0; b < 5; b++) {
        const int m = 1 << b;
        const int w = 5 + b;
#pragma unroll
        for (int r = 0; r < 32; r++) {
            if (r < m) {
                st[r + m] = st[r] * v[w];
                st[r]     = st[r] * u[w];
            }
        }
    }

    // ---- 6 layers (frame-tracked; cosines prescaled) ----
#pragma unroll
    for (int k = 0; k < 6; k++) {
        // (1) mixed CNOT(4,5)
        {
            const bool qsw = (__popc(lane & CK[k]) & 1);
#pragma unroll
            for (int i = 0; i < 16; i++) {
                float a = st[2 * i], b = st[2 * i + 1];
                st[2 * i]     = qsw ? b : a;
                st[2 * i + 1] = qsw ? a : b;
            }
        }
        // (2) reg CNOTs: free relabel
        {
            float tp[32];
#pragma unroll
            for (int r = 0; r < 32; r++) tp[r] = st[RSRC(r)];
#pragma unroll
            for (int r = 0; r < 32; r++) st[r] = tp[r];
        }
        // (3a) lane-RYs, wires 0-2: scalar fp32 shfl (issue-optimal)
#pragma unroll
        for (int w = 0; w < 3; w++) {
            const int m = MK[k][w];
            const float t = sqt[k][w];
            float tq = (__popc(lane & SK[k][w]) & 1) ? t : -t;
#pragma unroll
            for (int r = 0; r < 32; r++) {
                float o = __shfl_xor_sync(FULLMASK, st[r], m);
                st[r] = fmaf(tq, o, st[r]);
            }
        }
        // (3b) lane-RYs, wires 3-4: fp16x2-packed shfl (MIO relief).
        // Correction term tq*o computed in fp16 (|tq|<=0.025 -> error ~3e-5 rel).
#pragma unroll
        for (int w = 3; w < 5; w++) {
            const int m = MK[k][w];
            const float t = sqt[k][w];
            float tq = (__popc(lane & SK[k][w]) & 1) ? t : -t;
            unsigned tq2 = pack_h2(tq, tq);
#pragma unroll
            for (int j = 0; j < 16; j++) {
                unsigned hp = pack_h2(st[2 * j], st[2 * j + 1]);
                unsigned o  = __shfl_xor_sync(FULLMASK, hp, m);
                unsigned pr = hmul2_u(o, tq2);
                float2 pf = unpack_h2(pr);
                st[2 * j]     += pf.x;
                st[2 * j + 1] += pf.y;
            }
        }
        // (4) reg-RYs, wires 5-9 (bits 0-4)
#pragma unroll
        for (int b = 0; b < 5; b++) {
            float tw = sqt[k][5 + b];
            const int m = 1 << b;
#pragma unroll
            for (int r = 0; r < 32; r++) {
                if ((r & m) == 0) {
                    float a0 = st[r], a1 = st[r + m];
                    st[r]     = fmaf(-tw, a1, a0);
                    st[r + m] = fmaf( tw, a0, a1);
                }
            }
        }
    }

    // ---- measurement ----
    float T = 0.f;
#pragma unroll
    for (int r = 0; r < 32; r++) {
        st[r] = st[r] * st[r];
        T += st[r];
    }

    float e[10];
    // lane wires: signed WHT (5 shfl) + 5 broadcasts at rows of A6
    {
        float xwh = T;
#pragma unroll
        for (int j = 0; j < 5; j++) {
            float o = __shfl_xor_sync(FULLMASK, xwh, 1 << j);
            xwh = ((lane >> j) & 1) ? (o - xwh) : (xwh + o);
        }
#pragma unroll
        for (int w = 0; w < 5; w++)
            e[w] = __shfl_sync(FULLMASK, xwh, MROW[w]);
    }
    // reg wires 5..9: pair-tree over registers, then lane all-reduce
    {
        float p0[16], p1[8], p2[4], p3[2];
        float d0 = 0.f, d1 = 0.f, d2 = 0.f, d3 = 0.f, d4;
#pragma unroll
        for (int i = 0; i < 16; i++) { p0[i] = st[2*i] + st[2*i+1]; d0 += st[2*i] - st[2*i+1]; }
#pragma unroll
        for (int i = 0; i < 8; i++)  { p1[i] = p0[2*i] + p0[2*i+1]; d1 += p0[2*i] - p0[2*i+1]; }
#pragma unroll
        for (int i = 0; i < 4; i++)  { p2[i] = p1[2*i] + p1[2*i+1]; d2 += p1[2*i] - p1[2*i+1]; }
#pragma unroll
        for (int i = 0; i < 2; i++)  { p3[i] = p2[2*i] + p2[2*i+1]; d3 += p2[2*i] - p2[2*i+1]; }
        d4 = p3[0] - p3[1];
        float dd[5] = {d0, d1, d2, d3, d4};
#pragma unroll
        for (int b = 0; b < 5; b++) {
            float acc = dd[b];
#pragma unroll
            for (int off = 16; off; off >>= 1) acc += __shfl_xor_sync(FULLMASK, acc, off);
            e[5 + b] = acc;
        }
    }

    // ---- out = e @ W2 + b2 ----
#pragma unroll
    for (int t = 0; t < 2; t++) {
        int o = lane + 32 * t;
        float acc = sb2[o];
#pragma unroll
        for (int q = 0; q < 10; q++) acc = fmaf(e[q], sW2[q * 64 + o], acc);
        out[(size_t)sample * 64 + o] = acc;
    }
}

extern "C" void kernel_launch(void* const* d_in, const int* in_sizes, int n_in,
                              void* d_out, int out_size) {
    const float* x  = (const float*)d_in[0];
    const float* W1 = (const float*)d_in[1];
    const float* b1 = (const float*)d_in[2];
    const float* qw = (const float*)d_in[3];
    const float* W2 = (const float*)d_in[4];
    const float* b2 = (const float*)d_in[5];
    float* out = (float*)d_out;

    int B = in_sizes[0] / 512;          // 8192
    int grid = B / 8;                   // 8 samples (warps) per 256-thread block
    dq_kernel<<<grid, 256>>>(x, W1, b1, qw, W2, b2, out);
}

// round 9
// speedup vs baseline: 1.0402x; 1.0402x over previous
#include <cuda_runtime.h>
#include <math.h>

#define FULLMASK 0xffffffffu

// Composed register-bit CNOT relabel (wires 5..9 = reg bits 0..4), per layer:
#define RSRC(r) ( ((r)&1) \
    | (((((r)>>1)^(r))&1)<<1) \
    | (((((r)>>2)^((r)>>1)^(r))&1)<<2) \
    | (((((r)>>3)^((r)>>2))&1)<<3) \
    | (((((r)>>4)^((r)>>3)^((r)>>2))&1)<<4) )

// Frame-tracked lane-wire constants (A_k = (Mrev^-1)^k, verified round 4):
__device__ __constant__ const int MK[6][5] = {
    { 3,14,12,24,16},
    {13,26,20, 8,16},
    {23, 6,28,24,16},
    {17, 2, 4, 8,16},
    {19,14,12,24,16},
    {29,26,20, 8,16}
};
__device__ __constant__ const int SK[6][5] = {
    {1,3,7,12,28},
    {1,2,5,11,23},
    {1,3,6,14,25},
    {1,2,4,8,17},
    {1,3,7,12,29},
    {1,2,5,11,22}
};
__device__ __constant__ const int CK[6] = {16,28,23,25,17,29};
__device__ __constant__ const int MROW[5] = {1,2,5,11,22};

// Transposed W1 [q][d], written by a tiny pre-kernel each launch (deterministic).
__device__ float gW1T[10 * 512];

__device__ __forceinline__ float fast_tanh(float x) {
    float e;
    asm("ex2.approx.f32 %0, %1;" : "=f"(e) : "f"(x * 2.88539008177792681f));
    return (e - 1.0f) * __frcp_rn(e + 1.0f);
}

__global__ __launch_bounds__(256)
void transpose_w1_kernel(const float* __restrict__ W1) {
    int i = blockIdx.x * 256 + threadIdx.x;
    if (i < 5120) {
        int d = i / 10, q = i - d * 10;
        gW1T[q * 512 + d] = W1[i];
    }
}

__global__ __launch_bounds__(256, 5)
void dq_kernel(const float* __restrict__ x,
               const float* __restrict__ b1,
               const float* __restrict__ qw,
               const float* __restrict__ W2,
               const float* __restrict__ b2,
               float* __restrict__ out)
{
    __shared__ float sqt[6][10];     // tan(theta/2)
    __shared__ float sCt;            // prod of all 60 cos(theta/2)
    __shared__ float scc[64];

    const int tid = threadIdx.x;

    if (tid < 60) {
        float th = 0.5f * qw[tid];
        float s = __sinf(th), c = __cosf(th);
        sqt[tid / 10][tid % 10] = s * __frcp_rn(c);
        scc[tid] = c;
    }
    __syncthreads();
    if (tid == 0) {
        float p = 1.f;
#pragma unroll
        for (int i = 0; i < 60; i++) p *= scc[i];
        sCt = p;
    }
    __syncthreads();

    const int warp = tid >> 5;
    const int lane = tid & 31;
    const int sample = blockIdx.x * 8 + warp;
    const float* xr = x + (size_t)sample * 512;

    // ---- angles = tanh(x@W1 + b1) * pi/2; per-wire u/v ----
    const float4* x4 = (const float4*)xr;
    float4 xv[4];
#pragma unroll
    for (int t = 0; t < 4; t++) xv[t] = __ldg(&x4[lane + 32 * t]);

    float u[10], v[10];
#pragma unroll
    for (int q = 0; q < 10; q++) {
        const float4* w4 = (const float4*)(gW1T + q * 512);
        float p = 0.f;
#pragma unroll
        for (int t = 0; t < 4; t++) {
            float4 wv = __ldg(&w4[lane + 32 * t]);
            p = fmaf(xv[t].x, wv.x, p);
            p = fmaf(xv[t].y, wv.y, p);
            p = fmaf(xv[t].z, wv.z, p);
            p = fmaf(xv[t].w, wv.w, p);
        }
#pragma unroll
        for (int off = 16; off; off >>= 1) p += __shfl_xor_sync(FULLMASK, p, off);
        float ang = fast_tanh(p + __ldg(&b1[q])) * 1.57079632679489662f;
        float hh = 0.5f * ang;
        float sn = __sinf(hh), cs = __cosf(hh);
        u[q] = (cs - sn) * 0.70710678118654752f;
        v[q] = (cs + sn) * 0.70710678118654752f;
    }

    // ---- build product state, prescaled by the total deferred cosine ----
    float st[32];
    float L = sCt;
#pragma unroll
    for (int w = 0; w < 5; w++) L *= ((lane >> w) & 1) ? v[w] : u[w];
    st[0] = L;
#pragma unroll
    for (int b = 0; b < 5; b++) {
        const int m = 1 << b;
        const int w = 5 + b;
#pragma unroll
        for (int r = 0; r < 32; r++) {
            if (r < m) {
                st[r + m] = st[r] * v[w];
                st[r]     = st[r] * u[w];
            }
        }
    }

    // ---- 6 layers (frame-tracked; cosines prescaled) ----
#pragma unroll
    for (int k = 0; k < 6; k++) {
        // (1) mixed CNOT(4,5): ctrl = parity(lane & CK[k])
        {
            const bool qsw = (__popc(lane & CK[k]) & 1);
#pragma unroll
            for (int i = 0; i < 16; i++) {
                float a = st[2 * i], b = st[2 * i + 1];
                st[2 * i]     = qsw ? b : a;
                st[2 * i + 1] = qsw ? a : b;
            }
        }
        // (2) reg CNOTs: free compile-time relabel
        {
            float tp[32];
#pragma unroll
            for (int r = 0; r < 32; r++) tp[r] = st[RSRC(r)];
#pragma unroll
            for (int r = 0; r < 32; r++) st[r] = tp[r];
        }
        // (3) RY on lane wires (transformed frame)
#pragma unroll
        for (int w = 0; w < 5; w++) {
            const int m = MK[k][w];
            const float t = sqt[k][w];
            float tq = (__popc(lane & SK[k][w]) & 1) ? t : -t;
#pragma unroll
            for (int r = 0; r < 32; r++) {
                float o = __shfl_xor_sync(FULLMASK, st[r], m);
                st[r] = fmaf(tq, o, st[r]);
            }
        }
        // (4) RY on reg wires
#pragma unroll
        for (int b = 0; b < 5; b++) {
            float tw = sqt[k][5 + b];
            const int m = 1 << b;
#pragma unroll
            for (int r = 0; r < 32; r++) {
                if ((r & m) == 0) {
                    float a0 = st[r], a1 = st[r + m];
                    st[r]     = fmaf(-tw, a1, a0);
                    st[r + m] = fmaf( tw, a0, a1);
                }
            }
        }
    }

    // ---- measurement ----
    float T = 0.f;
#pragma unroll
    for (int r = 0; r < 32; r++) {
        st[r] = st[r] * st[r];
        T += st[r];
    }

    float e[10];
    // lane wires: signed WHT (5 shfl) + 5 broadcasts at rows of A6
    {
        float xwh = T;
#pragma unroll
        for (int j = 0; j < 5; j++) {
            float o = __shfl_xor_sync(FULLMASK, xwh, 1 << j);
            xwh = ((lane >> j) & 1) ? (o - xwh) : (xwh + o);
        }
#pragma unroll
        for (int w = 0; w < 5; w++)
            e[w] = __shfl_sync(FULLMASK, xwh, MROW[w]);
    }
    // reg wires 5..9: pair-tree over registers, then lane all-reduce
    {
        float p0[16], p1[8], p2[4], p3[2];
        float d0 = 0.f, d1 = 0.f, d2 = 0.f, d3 = 0.f, d4;
#pragma unroll
        for (int i = 0; i < 16; i++) { p0[i] = st[2*i] + st[2*i+1]; d0 += st[2*i] - st[2*i+1]; }
#pragma unroll
        for (int i = 0; i < 8; i++)  { p1[i] = p0[2*i] + p0[2*i+1]; d1 += p0[2*i] - p0[2*i+1]; }
#pragma unroll
        for (int i = 0; i < 4; i++)  { p2[i] = p1[2*i] + p1[2*i+1]; d2 += p1[2*i] - p1[2*i+1]; }
#pragma unroll
        for (int i = 0; i < 2; i++)  { p3[i] = p2[2*i] + p2[2*i+1]; d3 += p2[2*i] - p2[2*i+1]; }
        d4 = p3[0] - p3[1];
        float dd[5] = {d0, d1, d2, d3, d4};
#pragma unroll
        for (int b = 0; b < 5; b++) {
            float acc = dd[b];
#pragma unroll
            for (int off = 16; off; off >>= 1) acc += __shfl_xor_sync(FULLMASK, acc, off);
            e[5 + b] = acc;
        }
    }

    // ---- out = e @ W2 + b2 (W2/b2 straight from global; coalesced, L1-hit) ----
#pragma unroll
    for (int t = 0; t < 2; t++) {
        int o = lane + 32 * t;
        float acc = __ldg(&b2[o]);
#pragma unroll
        for (int q = 0; q < 10; q++) acc = fmaf(e[q], __ldg(&W2[q * 64 + o]), acc);
        out[(size_t)sample * 64 + o] = acc;
    }
}

extern "C" void kernel_launch(void* const* d_in, const int* in_sizes, int n_in,
                              void* d_out, int out_size) {
    const float* x  = (const float*)d_in[0];
    const float* W1 = (const float*)d_in[1];
    const float* b1 = (const float*)d_in[2];
    const float* qw = (const float*)d_in[3];
    const float* W2 = (const float*)d_in[4];
    const float* b2 = (const float*)d_in[5];
    float* out = (float*)d_out;

    // One-time-per-launch transpose of W1 into device-global gW1T (graph-safe).
    transpose_w1_kernel<<<20, 256>>>(W1);

    int B = in_sizes[0] / 512;          // 8192
    int grid = B / 8;                   // 8 samples (warps) per 256-thread block
    dq_kernel<<<grid, 256>>>(x, b1, qw, W2, b2, out);
}

// round 10
// speedup vs baseline: 1.0480x; 1.0075x over previous
#include <cuda_runtime.h>
#include <math.h>

#define FULLMASK 0xffffffffu

// Composed register-bit CNOT relabel (wires 5..9 = reg bits 0..4), per layer:
#define RSRC(r) ( ((r)&1) \
    | (((((r)>>1)^(r))&1)<<1) \
    | (((((r)>>2)^((r)>>1)^(r))&1)<<2) \
    | (((((r)>>3)^((r)>>2))&1)<<3) \
    | (((((r)>>4)^((r)>>3)^((r)>>2))&1)<<4) )

// Frame-tracked lane-wire constants (A_k = (Mrev^-1)^k, verified round 4):
__device__ __constant__ const int MK[6][5] = {
    { 3,14,12,24,16},
    {13,26,20, 8,16},
    {23, 6,28,24,16},
    {17, 2, 4, 8,16},
    {19,14,12,24,16},
    {29,26,20, 8,16}
};
__device__ __constant__ const int SK[6][5] = {
    {1,3,7,12,28},
    {1,2,5,11,23},
    {1,3,6,14,25},
    {1,2,4,8,17},
    {1,3,7,12,29},
    {1,2,5,11,22}
};
__device__ __constant__ const int CK[6] = {16,28,23,25,17,29};
__device__ __constant__ const int MROW[5] = {1,2,5,11,22};

// Transposed W1 [q][d], written by a tiny pre-kernel each launch (deterministic).
__device__ float gW1T[10 * 512];

__device__ __forceinline__ float fast_tanh(float x) {
    float e;
    asm("ex2.approx.f32 %0, %1;" : "=f"(e) : "f"(x * 2.88539008177792681f));
    return (e - 1.0f) * __frcp_rn(e + 1.0f);
}

__global__ __launch_bounds__(256)
void transpose_w1_kernel(const float* __restrict__ W1) {
    int i = blockIdx.x * 256 + threadIdx.x;
    if (i < 5120) {
        int d = i / 10, q = i - d * 10;
        gW1T[q * 512 + d] = W1[i];
    }
}

__global__ __launch_bounds__(128, 10)
void dq_kernel(const float* __restrict__ x,
               const float* __restrict__ b1,
               const float* __restrict__ qw,
               const float* __restrict__ W2,
               const float* __restrict__ b2,
               float* __restrict__ out)
{
    __shared__ float sqt[6][10];     // tan(theta/2)
    __shared__ float sCt;            // prod of all 60 cos(theta/2)
    __shared__ float scc[64];

    const int tid = threadIdx.x;

    if (tid < 60) {
        float th = 0.5f * qw[tid];
        float s = __sinf(th), c = __cosf(th);
        sqt[tid / 10][tid % 10] = s * __frcp_rn(c);
        scc[tid] = c;
    }
    __syncthreads();
    if (tid == 0) {
        float p = 1.f;
#pragma unroll
        for (int i = 0; i < 60; i++) p *= scc[i];
        sCt = p;
    }
    __syncthreads();

    const int warp = tid >> 5;
    const int lane = tid & 31;
    const int sample = blockIdx.x * 4 + warp;
    const float* xr = x + (size_t)sample * 512;

    // ---- angles = tanh(x@W1 + b1) * pi/2; per-wire u/v ----
    const float4* x4 = (const float4*)xr;
    float4 xv[4];
#pragma unroll
    for (int t = 0; t < 4; t++) xv[t] = __ldg(&x4[lane + 32 * t]);

    float u[10], v[10];
#pragma unroll
    for (int q = 0; q < 10; q++) {
        const float4* w4 = (const float4*)(gW1T + q * 512);
        float p = 0.f;
#pragma unroll
        for (int t = 0; t < 4; t++) {
            float4 wv = __ldg(&w4[lane + 32 * t]);
            p = fmaf(xv[t].x, wv.x, p);
            p = fmaf(xv[t].y, wv.y, p);
            p = fmaf(xv[t].z, wv.z, p);
            p = fmaf(xv[t].w, wv.w, p);
        }
#pragma unroll
        for (int off = 16; off; off >>= 1) p += __shfl_xor_sync(FULLMASK, p, off);
        float ang = fast_tanh(p + __ldg(&b1[q])) * 1.57079632679489662f;
        float hh = 0.5f * ang;
        float sn = __sinf(hh), cs = __cosf(hh);
        u[q] = (cs - sn) * 0.70710678118654752f;
        v[q] = (cs + sn) * 0.70710678118654752f;
    }

    // ---- build product state, prescaled by the total deferred cosine ----
    float st[32];
    float L = sCt;
#pragma unroll
    for (int w = 0; w < 5; w++) L *= ((lane >> w) & 1) ? v[w] : u[w];
    st[0] = L;
#pragma unroll
    for (int b = 0; b < 5; b++) {
        const int m = 1 << b;
        const int w = 5 + b;
#pragma unroll
        for (int r = 0; r < 32; r++) {
            if (r < m) {
                st[r + m] = st[r] * v[w];
                st[r]     = st[r] * u[w];
            }
        }
    }

    // ---- 6 layers (frame-tracked; cosines prescaled) ----
#pragma unroll
    for (int k = 0; k < 6; k++) {
        // (1) mixed CNOT(4,5): ctrl = parity(lane & CK[k])
        {
            const bool qsw = (__popc(lane & CK[k]) & 1);
#pragma unroll
            for (int i = 0; i < 16; i++) {
                float a = st[2 * i], b = st[2 * i + 1];
                st[2 * i]     = qsw ? b : a;
                st[2 * i + 1] = qsw ? a : b;
            }
        }
        // (2) reg CNOTs: free compile-time relabel
        {
            float tp[32];
#pragma unroll
            for (int r = 0; r < 32; r++) tp[r] = st[RSRC(r)];
#pragma unroll
            for (int r = 0; r < 32; r++) st[r] = tp[r];
        }
        // (3) RY on lane wires (transformed frame)
#pragma unroll
        for (int w = 0; w < 5; w++) {
            const int m = MK[k][w];
            const float t = sqt[k][w];
            float tq = (__popc(lane & SK[k][w]) & 1) ? t : -t;
#pragma unroll
            for (int r = 0; r < 32; r++) {
                float o = __shfl_xor_sync(FULLMASK, st[r], m);
                st[r] = fmaf(tq, o, st[r]);
            }
        }
        // (4) RY on reg wires
#pragma unroll
        for (int b = 0; b < 5; b++) {
            float tw = sqt[k][5 + b];
            const int m = 1 << b;
#pragma unroll
            for (int r = 0; r < 32; r++) {
                if ((r & m) == 0) {
                    float a0 = st[r], a1 = st[r + m];
                    st[r]     = fmaf(-tw, a1, a0);
                    st[r + m] = fmaf( tw, a0, a1);
                }
            }
        }
    }

    // ---- measurement ----
    float T = 0.f;
#pragma unroll
    for (int r = 0; r < 32; r++) {
        st[r] = st[r] * st[r];
        T += st[r];
    }

    float e[10];
    // lane wires: signed WHT (5 shfl) + 5 broadcasts at rows of A6
    {
        float xwh = T;
#pragma unroll
        for (int j = 0; j < 5; j++) {
            float o = __shfl_xor_sync(FULLMASK, xwh, 1 << j);
            xwh = ((lane >> j) & 1) ? (o - xwh) : (xwh + o);
        }
#pragma unroll
        for (int w = 0; w < 5; w++)
            e[w] = __shfl_sync(FULLMASK, xwh, MROW[w]);
    }
    // reg wires 5..9: pair-tree over registers, then lane all-reduce
    {
        float p0[16], p1[8], p2[4], p3[2];
        float d0 = 0.f, d1 = 0.f, d2 = 0.f, d3 = 0.f, d4;
#pragma unroll
        for (int i = 0; i < 16; i++) { p0[i] = st[2*i] + st[2*i+1]; d0 += st[2*i] - st[2*i+1]; }
#pragma unroll
        for (int i = 0; i < 8; i++)  { p1[i] = p0[2*i] + p0[2*i+1]; d1 += p0[2*i] - p0[2*i+1]; }
#pragma unroll
        for (int i = 0; i < 4; i++)  { p2[i] = p1[2*i] + p1[2*i+1]; d2 += p1[2*i] - p1[2*i+1]; }
#pragma unroll
        for (int i = 0; i < 2; i++)  { p3[i] = p2[2*i] + p2[2*i+1]; d3 += p2[2*i] - p2[2*i+1]; }
        d4 = p3[0] - p3[1];
        float dd[5] = {d0, d1, d2, d3, d4};
#pragma unroll
        for (int b = 0; b < 5; b++) {
            float acc = dd[b];
#pragma unroll
            for (int off = 16; off; off >>= 1) acc += __shfl_xor_sync(FULLMASK, acc, off);
            e[5 + b] = acc;
        }
    }

    // ---- out = e @ W2 + b2 (coalesced global reads; L1-resident) ----
#pragma unroll
    for (int t = 0; t < 2; t++) {
        int o = lane + 32 * t;
        float acc = __ldg(&b2[o]);
#pragma unroll
        for (int q = 0; q < 10; q++) acc = fmaf(e[q], __ldg(&W2[q * 64 + o]), acc);
        out[(size_t)sample * 64 + o] = acc;
    }
}

extern "C" void kernel_launch(void* const* d_in, const int* in_sizes, int n_in,
                              void* d_out, int out_size) {
    const float* x  = (const float*)d_in[0];
    const float* W1 = (const float*)d_in[1];
    const float* b1 = (const float*)d_in[2];
    const float* qw = (const float*)d_in[3];
    const float* W2 = (const float*)d_in[4];
    const float* b2 = (const float*)d_in[5];
    float* out = (float*)d_out;

    // One-time-per-launch transpose of W1 into device-global gW1T (graph-safe).
    transpose_w1_kernel<<<20, 256>>>(W1);

    int B = in_sizes[0] / 512;          // 8192
    int grid = B / 4;                   // 4 samples (warps) per 128-thread block
    dq_kernel<<<grid, 128>>>(x, b1, qw, W2, b2, out);
}

// round 11
// speedup vs baseline: 1.1230x; 1.0715x over previous
#include <cuda_runtime.h>
#include <math.h>

#define FULLMASK 0xffffffffu

// Composed register-bit CNOT relabel (wires 5..9 = reg bits 0..4), per layer:
#define RSRC(r) ( ((r)&1) \
    | (((((r)>>1)^(r))&1)<<1) \
    | (((((r)>>2)^((r)>>1)^(r))&1)<<2) \
    | (((((r)>>3)^((r)>>2))&1)<<3) \
    | (((((r)>>4)^((r)>>3)^((r)>>2))&1)<<4) )

// Frame-tracked lane-wire constants (A_k = (Mrev^-1)^k, verified round 4):
__device__ __constant__ const int MK[6][5] = {
    { 3,14,12,24,16},
    {13,26,20, 8,16},
    {23, 6,28,24,16},
    {17, 2, 4, 8,16},
    {19,14,12,24,16},
    {29,26,20, 8,16}
};
__device__ __constant__ const int SK[6][5] = {
    {1,3,7,12,28},
    {1,2,5,11,23},
    {1,3,6,14,25},
    {1,2,4,8,17},
    {1,3,7,12,29},
    {1,2,5,11,22}
};
__device__ __constant__ const int CK[6] = {16,28,23,25,17,29};
__device__ __constant__ const int MROW[5] = {1,2,5,11,22};

// Transposed W1 [q][d], written by a tiny pre-kernel each launch (deterministic).
__device__ float gW1T[10 * 512];

__device__ __forceinline__ float fast_tanh(float x) {
    float e;
    asm("ex2.approx.f32 %0, %1;" : "=f"(e) : "f"(x * 2.88539008177792681f));
    return (e - 1.0f) * __frcp_rn(e + 1.0f);
}

// True dual-fp32 FMA on the f32x2 pipe. float2 <-> double reinterpret is a
// register-pair no-op; no mov.b64 packing of scalars (the R7 mistake).
__device__ __forceinline__ float2 ffma2(float2 a, float2 b, float2 c) {
    double da = *reinterpret_cast<double*>(&a);
    double db = *reinterpret_cast<double*>(&b);
    double dc = *reinterpret_cast<double*>(&c);
    double dd;
    asm("fma.rn.f32x2 %0, %1, %2, %3;" : "=d"(dd) : "d"(da), "d"(db), "d"(dc));
    return *reinterpret_cast<float2*>(&dd);
}
__device__ __forceinline__ float2 fmul2(float2 a, float2 b) {
    double da = *reinterpret_cast<double*>(&a);
    double db = *reinterpret_cast<double*>(&b);
    double dd;
    asm("mul.rn.f32x2 %0, %1, %2;" : "=d"(dd) : "d"(da), "d"(db));
    return *reinterpret_cast<float2*>(&dd);
}

// half accessor for packed state: logical reg index r -> st[r>>1].x/.y
#define GETH(st, r) (((r) & 1) ? (st)[(r) >> 1].y : (st)[(r) >> 1].x)

__global__ __launch_bounds__(256)
void transpose_w1_kernel(const float* __restrict__ W1) {
    int i = blockIdx.x * 256 + threadIdx.x;
    if (i < 5120) {
        int d = i / 10, q = i - d * 10;
        gW1T[q * 512 + d] = W1[i];
    }
}

__global__ __launch_bounds__(128, 10)
void dq_kernel(const float* __restrict__ x,
               const float* __restrict__ b1,
               const float* __restrict__ qw,
               const float* __restrict__ W2,
               const float* __restrict__ b2,
               float* __restrict__ out)
{
    __shared__ float sqt[6][10];     // tan(theta/2)
    __shared__ float sCt;            // prod of all 60 cos(theta/2)
    __shared__ float scc[64];

    const int tid = threadIdx.x;

    if (tid < 60) {
        float th = 0.5f * qw[tid];
        float s = __sinf(th), c = __cosf(th);
        sqt[tid / 10][tid % 10] = s * __frcp_rn(c);
        scc[tid] = c;
    }
    __syncthreads();
    if (tid == 0) {
        float p = 1.f;
#pragma unroll
        for (int i = 0; i < 60; i++) p *= scc[i];
        sCt = p;
    }
    __syncthreads();

    const int warp = tid >> 5;
    const int lane = tid & 31;
    const int sample = blockIdx.x * 4 + warp;
    const float* xr = x + (size_t)sample * 512;

    // ---- angles = tanh(x@W1 + b1) * pi/2; per-wire u/v ----
    const float4* x4 = (const float4*)xr;
    float4 xv[4];
#pragma unroll
    for (int t = 0; t < 4; t++) xv[t] = __ldg(&x4[lane + 32 * t]);

    float u[10], v[10];
#pragma unroll
    for (int q = 0; q < 10; q++) {
        const float4* w4 = (const float4*)(gW1T + q * 512);
        float2 acc = make_float2(0.f, 0.f);
#pragma unroll
        for (int t = 0; t < 4; t++) {
            float4 wv = __ldg(&w4[lane + 32 * t]);
            acc = ffma2(make_float2(xv[t].x, xv[t].y), make_float2(wv.x, wv.y), acc);
            acc = ffma2(make_float2(xv[t].z, xv[t].w), make_float2(wv.z, wv.w), acc);
        }
        float p = acc.x + acc.y;
#pragma unroll
        for (int off = 16; off; off >>= 1) p += __shfl_xor_sync(FULLMASK, p, off);
        float ang = fast_tanh(p + __ldg(&b1[q])) * 1.57079632679489662f;
        float hh = 0.5f * ang;
        float sn = __sinf(hh), cs = __cosf(hh);
        u[q] = (cs - sn) * 0.70710678118654752f;
        v[q] = (cs + sn) * 0.70710678118654752f;
    }

    // ---- build product state (packed pairs: st[i] = {amp(2i), amp(2i+1)}) ----
    float2 st[16];
    {
        float L = sCt;
#pragma unroll
        for (int w = 0; w < 5; w++) L *= ((lane >> w) & 1) ? v[w] : u[w];
        // reg wire 5 (bit 0) splits within the pair:
        st[0].x = L * u[5];
        st[0].y = L * v[5];
        // reg wires 6..9 (packed-index bits 0..3):
#pragma unroll
        for (int b = 0; b < 4; b++) {
            const int m = 1 << b;
            const int w = 6 + b;
            float2 uu = make_float2(u[w], u[w]);
            float2 vv = make_float2(v[w], v[w]);
#pragma unroll
            for (int j = 0; j < 16; j++) {
                if (j < m) {
                    st[j + m] = fmul2(st[j], vv);
                    st[j]     = fmul2(st[j], uu);
                }
            }
        }
    }

    // ---- 6 layers (frame-tracked; cosines prescaled) ----
#pragma unroll
    for (int k = 0; k < 6; k++) {
        // (1) mixed CNOT(4,5): conditional within-pair swap
        {
            const bool qsw = (__popc(lane & CK[k]) & 1);
#pragma unroll
            for (int j = 0; j < 16; j++) {
                float a = st[j].x, b = st[j].y;
                st[j].x = qsw ? b : a;
                st[j].y = qsw ? a : b;
            }
        }
        // (2) reg CNOTs: compile-time half-gather relabel
        {
            float2 tp[16];
#pragma unroll
            for (int j = 0; j < 16; j++) {
                tp[j].x = GETH(st, RSRC(2 * j));
                tp[j].y = GETH(st, RSRC(2 * j + 1));
            }
#pragma unroll
            for (int j = 0; j < 16; j++) st[j] = tp[j];
        }
        // (3) lane-RYs: 2 SHFL + 1 FFMA2 per packed pair
#pragma unroll
        for (int w = 0; w < 5; w++) {
            const int m = MK[k][w];
            const float t = sqt[k][w];
            float tq = (__popc(lane & SK[k][w]) & 1) ? t : -t;
            float2 t2 = make_float2(tq, tq);
#pragma unroll
            for (int j = 0; j < 16; j++) {
                float2 o;
                o.x = __shfl_xor_sync(FULLMASK, st[j].x, m);
                o.y = __shfl_xor_sync(FULLMASK, st[j].y, m);
                st[j] = ffma2(t2, o, st[j]);
            }
        }
        // (4a) reg-RY wire 5 (within-pair, scalar)
        {
            float tw = sqt[k][5];
#pragma unroll
            for (int j = 0; j < 16; j++) {
                float a0 = st[j].x, a1 = st[j].y;
                st[j].x = fmaf(-tw, a1, a0);
                st[j].y = fmaf( tw, a0, a1);
            }
        }
        // (4b) reg-RY wires 6-9 (cross-pair, FFMA2)
#pragma unroll
        for (int b = 0; b < 4; b++) {
            float tw = sqt[k][6 + b];
            float2 nt2 = make_float2(-tw, -tw);
            float2 pt2 = make_float2( tw,  tw);
            const int M = 1 << b;
#pragma unroll
            for (int j = 0; j < 16; j++) {
                if ((j & M) == 0) {
                    float2 A = st[j], B = st[j + M];
                    st[j]     = ffma2(nt2, B, A);
                    st[j + M] = ffma2(pt2, A, B);
                }
            }
        }
    }

    // ---- measurement ----
#pragma unroll
    for (int j = 0; j < 16; j++) st[j] = fmul2(st[j], st[j]);

    float e[10];
    float T;
    // reg wires 5..9: pair-tree over packed halves, then lane all-reduce
    {
        float p0[16], p1[8], p2[4], p3[2];
        float d0 = 0.f, d1 = 0.f, d2 = 0.f, d3 = 0.f, d4;
#pragma unroll
        for (int i = 0; i < 16; i++) { p0[i] = st[i].x + st[i].y; d0 += st[i].x - st[i].y; }
#pragma unroll
        for (int i = 0; i < 8; i++)  { p1[i] = p0[2*i] + p0[2*i+1]; d1 += p0[2*i] - p0[2*i+1]; }
#pragma unroll
        for (int i = 0; i < 4; i++)  { p2[i] = p1[2*i] + p1[2*i+1]; d2 += p1[2*i] - p1[2*i+1]; }
#pragma unroll
        for (int i = 0; i < 2; i++)  { p3[i] = p2[2*i] + p2[2*i+1]; d3 += p2[2*i] - p2[2*i+1]; }
        d4 = p3[0] - p3[1];
        T  = p3[0] + p3[1];
        float dd[5] = {d0, d1, d2, d3, d4};
#pragma unroll
        for (int b = 0; b < 5; b++) {
            float acc = dd[b];
#pragma unroll
            for (int off = 16; off; off >>= 1) acc += __shfl_xor_sync(FULLMASK, acc, off);
            e[5 + b] = acc;
        }
    }
    // lane wires: signed WHT (5 shfl) + 5 broadcasts at rows of A6
    {
        float xwh = T;
#pragma unroll
        for (int j = 0; j < 5; j++) {
            float o = __shfl_xor_sync(FULLMASK, xwh, 1 << j);
            xwh = ((lane >> j) & 1) ? (o - xwh) : (xwh + o);
        }
#pragma unroll
        for (int w = 0; w < 5; w++)
            e[w] = __shfl_sync(FULLMASK, xwh, MROW[w]);
    }

    // ---- out = e @ W2 + b2 (coalesced global reads; L1-resident) ----
#pragma unroll
    for (int t = 0; t < 2; t++) {
        int o = lane + 32 * t;
        float acc = __ldg(&b2[o]);
#pragma unroll
        for (int q = 0; q < 10; q++) acc = fmaf(e[q], __ldg(&W2[q * 64 + o]), acc);
        out[(size_t)sample * 64 + o] = acc;
    }
}

extern "C" void kernel_launch(void* const* d_in, const int* in_sizes, int n_in,
                              void* d_out, int out_size) {
    const float* x  = (const float*)d_in[0];
    const float* W1 = (const float*)d_in[1];
    const float* b1 = (const float*)d_in[2];
    const float* qw = (const float*)d_in[3];
    const float* W2 = (const float*)d_in[4];
    const float* b2 = (const float*)d_in[5];
    float* out = (float*)d_out;

    // One-time-per-launch transpose of W1 into device-global gW1T (graph-safe).
    transpose_w1_kernel<<<20, 256>>>(W1);

    int B = in_sizes[0] / 512;          // 8192
    int grid = B / 4;                   // 4 samples (warps) per 128-thread block
    dq_kernel<<<grid, 128>>>(x, b1, qw, W2, b2, out);
}